// round 1
// baseline (speedup 1.0000x reference)
#include <cuda_runtime.h>

// Problem constants (fixed shapes)
#define BB   4
#define SS   4096
#define DD   2048
#define DH   1024
#define MTOK (BB * SS)   // 16384 tokens

// Scratch (static device globals; no allocations allowed)
__device__ float g_o1[(size_t)MTOK * DH];   // conv1 output   (64 MB)
__device__ float g_y [(size_t)MTOK * DD];   // pre-norm y     (128 MB)

// ---------------------------------------------------------------------------
// Fused 2-tap temporal conv as GEMM:
//   C[g, n] = sum_k W[n,k,0]*A[g-1, k] + W[n,k,1]*A[g, k] + bias[n] (+ resid)
// where A[g-1] at a batch boundary comes from cache[b, :].
// Tile: BM=128 tokens x BN=128 outs x BK=16. A-tile holds 129 rows
// (tokens g0-1 .. g0+127); prev(row i) = As[i], cur(row i) = As[i+1].
// S % BM == 0 so only the first A-tile row can cross a batch boundary.
// ---------------------------------------------------------------------------
template <int K, bool HAS_RESID>
__global__ __launch_bounds__(256, 2)
void conv_gemm(const float* __restrict__ A,      // [MTOK, K]
               const float* __restrict__ cache,  // [BB, K]
               const float* __restrict__ W,      // [N, K, 2]
               const float* __restrict__ bias,   // [N]
               const float* __restrict__ resid,  // [MTOK, N] (if HAS_RESID)
               float* __restrict__ C,            // [MTOK, N]
               int N)
{
    constexpr int BM = 128, BN = 128, BK = 16;
    constexpr int LDA = BM + 4;  // 132: 16B-aligned rows, bank offset 4/row
    __shared__ float As [BK][LDA];   // As[k][r], r = 0..128
    __shared__ float Bs0[BK][LDA];
    __shared__ float Bs1[BK][LDA];

    const int tid = threadIdx.x;
    const int g0  = blockIdx.y * BM;
    const int n0  = blockIdx.x * BN;
    const int b   = g0 / SS;
    const bool atBoundary = (g0 % SS) == 0;

    const int ty = tid >> 4;          // 0..15 -> row group
    const int tx = tid & 15;          // 0..15 -> col group

    float acc[2][4][2][4];
    #pragma unroll
    for (int r = 0; r < 2; r++)
        #pragma unroll
        for (int i = 0; i < 4; i++)
            #pragma unroll
            for (int c = 0; c < 2; c++)
                #pragma unroll
                for (int j = 0; j < 4; j++)
                    acc[r][i][c][j] = 0.f;

    for (int k0 = 0; k0 < K; k0 += BK) {
        // ---- load A tile: 129 rows x 16 cols, float4 per slot ----
        #pragma unroll
        for (int idx = tid; idx < 129 * 4; idx += 256) {
            int r  = idx >> 2;
            int c4 = (idx & 3) * 4;
            const float* src;
            if (r == 0 && atBoundary)
                src = cache + (size_t)b * K + k0 + c4;
            else
                src = A + (size_t)(g0 - 1 + r) * K + k0 + c4;
            float4 v = *(const float4*)src;
            As[c4 + 0][r] = v.x;
            As[c4 + 1][r] = v.y;
            As[c4 + 2][r] = v.z;
            As[c4 + 3][r] = v.w;
        }
        // ---- load W tile: 128 outs x 16 k, tap pair as float2 ----
        #pragma unroll
        for (int idx = tid; idx < BN * BK / 8; idx += 256) {
            // 8 consecutive (n,k) pairs per thread? keep simple: 1 float2 each
        }
        for (int idx = tid; idx < BN * BK; idx += 256) {
            int n = idx >> 4;
            int k = idx & 15;
            float2 v = *(const float2*)(W + ((size_t)(n0 + n) * K + (k0 + k)) * 2);
            Bs0[k][n] = v.x;
            Bs1[k][n] = v.y;
        }
        __syncthreads();

        #pragma unroll
        for (int k = 0; k < BK; k++) {
            float a[2][5];
            #pragma unroll
            for (int r = 0; r < 2; r++) {
                int rb = r * 64 + ty * 4;
                float4 t = *(const float4*)&As[k][rb];
                a[r][0] = t.x; a[r][1] = t.y; a[r][2] = t.z; a[r][3] = t.w;
                a[r][4] = As[k][rb + 4];
            }
            float4 b0v[2], b1v[2];
            #pragma unroll
            for (int c = 0; c < 2; c++) {
                int cb = c * 64 + tx * 4;
                b0v[c] = *(const float4*)&Bs0[k][cb];
                b1v[c] = *(const float4*)&Bs1[k][cb];
            }
            #pragma unroll
            for (int r = 0; r < 2; r++) {
                #pragma unroll
                for (int c = 0; c < 2; c++) {
                    float b0a[4] = {b0v[c].x, b0v[c].y, b0v[c].z, b0v[c].w};
                    float b1a[4] = {b1v[c].x, b1v[c].y, b1v[c].z, b1v[c].w};
                    #pragma unroll
                    for (int i = 0; i < 4; i++)
                        #pragma unroll
                        for (int j = 0; j < 4; j++)
                            acc[r][i][c][j] += a[r][i] * b0a[j] + a[r][i + 1] * b1a[j];
                }
            }
        }
        __syncthreads();
    }

    // ---- epilogue: + bias (+ residual) ----
    #pragma unroll
    for (int r = 0; r < 2; r++) {
        #pragma unroll
        for (int i = 0; i < 4; i++) {
            int g = g0 + r * 64 + ty * 4 + i;
            #pragma unroll
            for (int c = 0; c < 2; c++) {
                #pragma unroll
                for (int j = 0; j < 4; j++) {
                    int n = n0 + c * 64 + tx * 4 + j;
                    float v = acc[r][i][c][j] + bias[n];
                    if (HAS_RESID) v += resid[(size_t)g * N + n];
                    C[(size_t)g * N + n] = v;
                }
            }
        }
    }
}

// ---------------------------------------------------------------------------
// RMSNorm over D=2048, one CTA per token row.
// ---------------------------------------------------------------------------
__global__ __launch_bounds__(256)
void rmsnorm_kernel(const float* __restrict__ y,
                    const float* __restrict__ ln_w,
                    float* __restrict__ out)
{
    const int g = blockIdx.x;
    const float4* row = (const float4*)(y + (size_t)g * DD);
    float4 v[2];
    float s = 0.f;
    #pragma unroll
    for (int r = 0; r < 2; r++) {
        v[r] = row[threadIdx.x + r * 256];
        s += v[r].x * v[r].x + v[r].y * v[r].y + v[r].z * v[r].z + v[r].w * v[r].w;
    }
    // block reduce
    __shared__ float red[8];
    #pragma unroll
    for (int o = 16; o; o >>= 1) s += __shfl_down_sync(0xffffffffu, s, o);
    if ((threadIdx.x & 31) == 0) red[threadIdx.x >> 5] = s;
    __syncthreads();
    if (threadIdx.x < 32) {
        float t = (threadIdx.x < 8) ? red[threadIdx.x] : 0.f;
        #pragma unroll
        for (int o = 4; o; o >>= 1) t += __shfl_down_sync(0xffffffffu, t, o);
        if (threadIdx.x == 0) red[0] = t;
    }
    __syncthreads();
    const float inv = rsqrtf(red[0] * (1.0f / DD) + 1e-6f);
    float4* orow = (float4*)(out + (size_t)g * DD);
    const float4* wrow = (const float4*)ln_w;
    #pragma unroll
    for (int r = 0; r < 2; r++) {
        float4 w = wrow[threadIdx.x + r * 256];
        float4 o;
        o.x = v[r].x * inv * w.x;
        o.y = v[r].y * inv * w.y;
        o.z = v[r].z * inv * w.z;
        o.w = v[r].w * inv * w.w;
        orow[threadIdx.x + r * 256] = o;
    }
}

// ---------------------------------------------------------------------------
// New caches: lf1 = x[:, S-1, :] (BxD), lf2 = o1[:, S-1, :] (BxDH)
// ---------------------------------------------------------------------------
__global__ void write_caches(const float* __restrict__ x,
                             const float* __restrict__ o1,
                             float* __restrict__ out_lf1,
                             float* __restrict__ out_lf2)
{
    int i = blockIdx.x * blockDim.x + threadIdx.x;
    if (i < BB * DD) {
        int b = i / DD, d = i % DD;
        out_lf1[i] = x[((size_t)b * SS + SS - 1) * DD + d];
    }
    if (i < BB * DH) {
        int b = i / DH, e = i % DH;
        out_lf2[i] = o1[((size_t)b * SS + SS - 1) * DH + e];
    }
}

extern "C" void kernel_launch(void* const* d_in, const int* in_sizes, int n_in,
                              void* d_out, int out_size)
{
    const float* x    = (const float*)d_in[0];  // [B*S, D]
    const float* lf1c = (const float*)d_in[1];  // [B, D]
    const float* lf2c = (const float*)d_in[2];  // [B, DH]
    const float* w1   = (const float*)d_in[3];  // [DH, D, 2]
    const float* b1   = (const float*)d_in[4];  // [DH]
    const float* w2   = (const float*)d_in[5];  // [D, DH, 2]
    const float* b2   = (const float*)d_in[6];  // [D]
    const float* lnw  = (const float*)d_in[7];  // [D]
    float* out = (float*)d_out;

    float *o1, *y;
    cudaGetSymbolAddress((void**)&o1, g_o1);
    cudaGetSymbolAddress((void**)&y,  g_y);

    // conv1: [MTOK, D] -> [MTOK, DH]
    {
        dim3 grid(DH / 128, MTOK / 128);
        conv_gemm<DD, false><<<grid, 256>>>(x, lf1c, w1, b1, nullptr, o1, DH);
    }
    // conv2 + bias + residual: [MTOK, DH] -> [MTOK, D], y = o2 + x
    {
        dim3 grid(DD / 128, MTOK / 128);
        conv_gemm<DH, true><<<grid, 256>>>(o1, lf2c, w2, b2, x, y, DD);
    }
    // RMSNorm -> lf_output
    rmsnorm_kernel<<<MTOK, 256>>>(y, lnw, out);

    // caches appended after lf_output if the output buffer carries them
    const long long main_sz = (long long)MTOK * DD;
    if ((long long)out_size >= main_sz + BB * DD + BB * DH) {
        write_caches<<<(BB * DD + 255) / 256, 256>>>(
            x, o1, out + main_sz, out + main_sz + BB * DD);
    }
}